// round 17
// baseline (speedup 1.0000x reference)
#include <cuda_runtime.h>
#include <cuda_bf16.h>
#include <cstdint>

#define B_ 32
#define L_ 2048
#define S_ 8
#define HALO 8
#define OUT_ROWS 18424
#define TILE_L 56
#define ROWS_T 64            // TILE_L + HALO
#define NTILES 37            // ceil(2048/56)
#define THREADS 256          // 8 warps: (gemm, m-half, n-half)
#define BSTR 72              // bf16 matrix row stride (elements) -> 144B
#define ROWP 68              // Ps/Qs row stride in floats

// dynamic smem layout (bytes):
// phase 1: A_hi@0(9216) A_lo@9216 W_hi@18432 W_lo@27648 BB_hi@36864 BB_lo@46080 -> 55296
// phase 2 alias: Ps@0 (64*68*4=17408), Qs@17408 -> 34816
#define OFF_A_HI 0
#define OFF_A_LO 9216
#define OFF_W_HI 18432
#define OFF_W_LO 27648
#define OFF_BB_HI 36864
#define OFF_BB_LO 46080
#define OFF_PS 0
#define OFF_QS 17408
#define DYN_SMEM 55296

// one-shot pre-split bf16 weights (written by setup kernel; 32 KB, L2-hot)
__device__ __nv_bfloat16 g_Whi[64 * 64];   // [o][c]
__device__ __nv_bfloat16 g_Wlo[64 * 64];
__device__ __nv_bfloat16 g_Bhi[64 * 64];   // [o][c] = bias[c][o] transposed
__device__ __nv_bfloat16 g_Blo[64 * 64];

__global__ void convert_wb_kernel(const float* __restrict__ W,
                                  const float* __restrict__ bias) {
    int idx = blockIdx.x * 256 + threadIdx.x;   // 16 blocks x 256 = 4096
    int o = idx >> 6, c = idx & 63;
    float w = W[idx];
    __nv_bfloat16 wh = __float2bfloat16(w);
    g_Whi[idx] = wh;
    g_Wlo[idx] = __float2bfloat16(w - __bfloat162float(wh));
    float bb = bias[c * 64 + o];
    __nv_bfloat16 bh = __float2bfloat16(bb);
    g_Bhi[idx] = bh;
    g_Blo[idx] = __float2bfloat16(bb - __bfloat162float(bh));
}

// m16n8k16 bf16 mma with f32 accumulate (sm_80+ PTX -> HMMA on sm_100)
static __device__ __forceinline__ void mma16816(float* d, uint32_t a0, uint32_t a1,
                                                uint32_t a2, uint32_t a3,
                                                uint32_t b0, uint32_t b1) {
    asm volatile(
        "mma.sync.aligned.m16n8k16.row.col.f32.bf16.bf16.f32 "
        "{%0,%1,%2,%3}, {%4,%5,%6,%7}, {%8,%9}, {%0,%1,%2,%3};"
        : "+f"(d[0]), "+f"(d[1]), "+f"(d[2]), "+f"(d[3])
        : "r"(a0), "r"(a1), "r"(a2), "r"(a3), "r"(b0), "r"(b1));
}

// bf16 hi/lo split of a float pair, packed bf16x2 (first element in low half)
static __device__ __forceinline__ void split2(float a, float b, uint32_t& h, uint32_t& l) {
    __nv_bfloat16 ah = __float2bfloat16(a), bh = __float2bfloat16(b);
    __nv_bfloat16 al = __float2bfloat16(a - __bfloat162float(ah));
    __nv_bfloat16 bl = __float2bfloat16(b - __bfloat162float(bh));
    h = (uint32_t)*(uint16_t*)&ah | ((uint32_t)*(uint16_t*)&bh << 16);
    l = (uint32_t)*(uint16_t*)&al | ((uint32_t)*(uint16_t*)&bl << 16);
}
static __device__ __forceinline__ void split4(const float* f, uint2& h, uint2& l) {
    split2(f[0], f[1], h.x, l.x);
    split2(f[2], f[3], h.y, l.y);
}

// non_pad_mask dtype probe (lengths >= L/2 so mask[0,0..1] true).
static __device__ __forceinline__ int mask_kind(const unsigned char* m) {
    unsigned char b0 = m[0], b1 = m[1];
    if (b0 == 1 && b1 != 0) return 0;
    if (b0 == 1) return 1;
    return 2;
}

__global__ __launch_bounds__(THREADS, 3) void fused_kernel(const float* __restrict__ times,
                                                           const float* __restrict__ F,
                                                           const void* __restrict__ maskp,
                                                           const float* __restrict__ usample,
                                                           float* __restrict__ out) {
    extern __shared__ __align__(16) char smem[];
    __shared__ float ts[ROWS_T + 2];
    __shared__ float vsf[ROWS_T + 2];
    __shared__ float us[S_];

    int tid = threadIdx.x, wid = tid >> 5, lane = tid & 31;
    int b = blockIdx.y;
    int tileStart = blockIdx.x * TILE_L;
    const float* gF = F + (size_t)b * L_ * 64;

    // ---- phase 0a: copy pre-split W/BB bf16 (global, L2-hot) into padded smem ----
    // 512 uint4 per array; STS.128 rows are 144B apart but each 8-lane phase covers
    // one 128B row segment -> conflict-free.
    {
#pragma unroll
        for (int k = 0; k < 2; k++) {
            int i = tid + k * 256;
            int row = i >> 3, ch = i & 7;
            uint32_t off = (uint32_t)(row * BSTR + ch * 8) * 2;
            *(uint4*)(smem + OFF_W_HI + off)  = ((const uint4*)g_Whi)[i];
            *(uint4*)(smem + OFF_W_LO + off)  = ((const uint4*)g_Wlo)[i];
            *(uint4*)(smem + OFF_BB_HI + off) = ((const uint4*)g_Bhi)[i];
            *(uint4*)(smem + OFF_BB_LO + off) = ((const uint4*)g_Blo)[i];
        }
    }
    // ---- phase 0b: convert A = F halo tile (64 rows x 64 c) to bf16 hi/lo ----
    {
        int row = tid >> 2, q = tid & 3;
        int gl = tileStart - HALO + row;
        bool ok = (gl >= 0 && gl < L_);
        const float* fr = gF + (size_t)(ok ? gl : 0) * 64 + q * 16;
#pragma unroll
        for (int j = 0; j < 4; j++) {
            float f4v[4];
            if (ok) *(float4*)f4v = ((const float4*)fr)[j];
            else { f4v[0] = f4v[1] = f4v[2] = f4v[3] = 0.f; }
            uint2 h, l;
            split4(f4v, h, l);
            uint32_t off = (uint32_t)(row * BSTR + q * 16 + j * 4) * 2;
            *(uint2*)(smem + OFF_A_HI + off) = h;
            *(uint2*)(smem + OFF_A_LO + off) = l;
        }
    }
    if (tid < ROWS_T + 1) {
        int kind = mask_kind((const unsigned char*)maskp);
        int gl = tileStart - HALO + tid;
        float t = 0.f, v = 0.f;
        if (gl >= 0 && gl < L_) {
            int mi = b * L_ + gl;
            t = times[mi];
            bool mv;
            if (kind == 0)      mv = ((const unsigned char*)maskp)[mi] != 0;
            else if (kind == 1) mv = ((const int*)maskp)[mi] != 0;
            else                mv = ((const float*)maskp)[mi] != 0.f;
            v = mv ? 1.f : 0.f;
        }
        ts[tid] = t;
        vsf[tid] = v;
    }
    if (tid < S_) us[tid] = usample[tid];
    __syncthreads();

    // ---- phase 1: tensor-core GEMM, 32x32 warp tiles ----
    // warp = (gemm = wid>>2, m-half = (wid>>1)&1, n-half = wid&1)
    int gemm = wid >> 2;
    int mh = (wid >> 1) & 1, nh = wid & 1;
    int g = lane >> 2, t4 = lane & 3;

    float acc[2][4][4];   // [mt][nt][frag]
#pragma unroll
    for (int mt = 0; mt < 2; mt++)
#pragma unroll
        for (int nt = 0; nt < 4; nt++)
#pragma unroll
            for (int z = 0; z < 4; z++) acc[mt][nt][z] = 0.f;

    const char* Ahi = smem + OFF_A_HI;
    const char* Alo = smem + OFF_A_LO;
    const char* Bhi = smem + (gemm ? OFF_BB_HI : OFF_W_HI);
    const char* Blo = smem + (gemm ? OFF_BB_LO : OFF_W_LO);

#pragma unroll
    for (int split = 0; split < 3; split++) {
        const char* Ab = (split < 2) ? Ahi : Alo;
        const char* Bb = (split == 1) ? Blo : Bhi;
#pragma unroll
        for (int k4 = 0; k4 < 4; k4++) {
            int k = k4 * 16 + t4 * 2;
            uint32_t a[2][4];
#pragma unroll
            for (int mt = 0; mt < 2; mt++) {
                int r = mh * 32 + mt * 16 + g;
                a[mt][0] = *(const uint32_t*)(Ab + (r * BSTR + k) * 2);
                a[mt][1] = *(const uint32_t*)(Ab + ((r + 8) * BSTR + k) * 2);
                a[mt][2] = *(const uint32_t*)(Ab + (r * BSTR + k + 8) * 2);
                a[mt][3] = *(const uint32_t*)(Ab + ((r + 8) * BSTR + k + 8) * 2);
            }
#pragma unroll
            for (int nt = 0; nt < 4; nt++) {
                int rn = nh * 32 + nt * 8 + g;
                uint32_t b0 = *(const uint32_t*)(Bb + (rn * BSTR + k) * 2);
                uint32_t b1 = *(const uint32_t*)(Bb + (rn * BSTR + k + 8) * 2);
                mma16816(acc[0][nt], a[0][0], a[0][1], a[0][2], a[0][3], b0, b1);
                mma16816(acc[1][nt], a[1][0], a[1][1], a[1][2], a[1][3], b0, b1);
            }
        }
    }
    __syncthreads();   // all smem GEMM-input reads done -> safe to alias Ps/Qs

    // masked writeback: Ps = m_j * P, Qs = m_j * Q
    {
        float* Dst = (float*)(smem + (gemm ? OFF_QS : OFF_PS));
#pragma unroll
        for (int mt = 0; mt < 2; mt++) {
            int r0 = mh * 32 + mt * 16 + g;
            float mr0 = vsf[r0], mr8 = vsf[r0 + 8];
#pragma unroll
            for (int nt = 0; nt < 4; nt++) {
                int col = nh * 32 + nt * 8 + t4 * 2;
                *(float2*)&Dst[r0 * ROWP + col] =
                    make_float2(acc[mt][nt][0] * mr0, acc[mt][nt][1] * mr0);
                *(float2*)&Dst[(r0 + 8) * ROWP + col] =
                    make_float2(acc[mt][nt][2] * mr8, acc[mt][nt][3] * mr8);
            }
        }
    }
    __syncthreads();

    // ---- phase 2: sliding-window combine over 56 l's ----
    // real[l] = m_l*(t_l*A + E),   A = sum_{j=l-8..l-1} mP_j,  E = sum (mQ_j - t_j*mP_j)
    // sim[l]  = m_l*(t_l*An + En), An/En advanced to j=l-7..l (8 taps); sum_lin = m_l*An.
    // 256 threads = 16 o4-lanes x 16 chunks (8x4 + 8x3 = 56).
    {
        const float* Ps = (const float*)(smem + OFF_PS);
        const float* Qs = (const float*)(smem + OFF_QS);
        int o4 = (tid & 15) * 4;
        int ck = tid >> 4;                       // 0..15
        int l0  = ck < 8 ? ck * 4 : 32 + (ck - 8) * 3;
        int len = ck < 8 ? 4 : 3;

        float4 A = make_float4(0.f, 0.f, 0.f, 0.f);
        float4 E = make_float4(0.f, 0.f, 0.f, 0.f);
#pragma unroll
        for (int i = 0; i < 8; i++) {            // init window rows l0..l0+7
            int r = l0 + i;
            float4 p = *(const float4*)&Ps[r * ROWP + o4];
            float4 q = *(const float4*)&Qs[r * ROWP + o4];
            float t = ts[r];
            A.x += p.x; A.y += p.y; A.z += p.z; A.w += p.w;
            E.x += fmaf(-t, p.x, q.x); E.y += fmaf(-t, p.y, q.y);
            E.z += fmaf(-t, p.z, q.z); E.w += fmaf(-t, p.w, q.w);
        }

#pragma unroll
        for (int i = 0; i < 4; i++) {
            if (i >= len) break;
            int ll = l0 + i;
            int l = tileStart + ll;
            if (l >= L_) break;
            float tl = ts[ll + HALO];
            float m  = vsf[ll + HALO];

            float4 pn = *(const float4*)&Ps[(ll + HALO) * ROWP + o4];   // new tap j=l
            float4 qn = *(const float4*)&Qs[(ll + HALO) * ROWP + o4];
            float4 po = *(const float4*)&Ps[ll * ROWP + o4];            // old tap j=l-8
            float4 qo = *(const float4*)&Qs[ll * ROWP + o4];
            float to = ts[ll];

            float4 An, En;
            An.x = A.x + pn.x - po.x; An.y = A.y + pn.y - po.y;
            An.z = A.z + pn.z - po.z; An.w = A.w + pn.w - po.w;
            En.x = fmaf(to, po.x, fmaf(-tl, pn.x, E.x + qn.x) - qo.x);
            En.y = fmaf(to, po.y, fmaf(-tl, pn.y, E.y + qn.y) - qo.y);
            En.z = fmaf(to, po.z, fmaf(-tl, pn.z, E.z + qn.z) - qo.z);
            En.w = fmaf(to, po.w, fmaf(-tl, pn.w, E.w + qn.w) - qo.w);

            float4 re, sbv, sl;
            re.x = m * fmaf(tl, A.x, E.x);    re.y = m * fmaf(tl, A.y, E.y);
            re.z = m * fmaf(tl, A.z, E.z);    re.w = m * fmaf(tl, A.w, E.w);
            sbv.x = m * fmaf(tl, An.x, En.x); sbv.y = m * fmaf(tl, An.y, En.y);
            sbv.z = m * fmaf(tl, An.z, En.z); sbv.w = m * fmaf(tl, An.w, En.w);
            sl.x = m * An.x; sl.y = m * An.y; sl.z = m * An.z; sl.w = m * An.w;

            float* ob = out + ((size_t)b * OUT_ROWS + (size_t)l * 9) * 64 + o4;
            *(float4*)ob = re;

            if (l < L_ - 1) {
                float udt = (m != 0.f && vsf[ll + HALO + 1] != 0.f)
                                ? (ts[ll + HALO + 1] - tl) : 0.f;
#pragma unroll
                for (int s = 0; s < S_; s++) {
                    float f = udt * us[s];
                    float4 v = make_float4(fmaf(f, sl.x, sbv.x), fmaf(f, sl.y, sbv.y),
                                           fmaf(f, sl.z, sbv.z), fmaf(f, sl.w, sbv.w));
                    *(float4*)(ob + (s + 1) * 64) = v;
                }
            }
            A = An;
            E = En;
        }
    }
}

extern "C" void kernel_launch(void* const* d_in, const int* in_sizes, int n_in,
                              void* d_out, int out_size) {
    const float* times    = (const float*)d_in[0];
    const float* features = (const float*)d_in[1];
    const void*  mask     = d_in[2];
    const float* usample  = (const float*)d_in[3];
    const float* W        = (const float*)d_in[4];
    const float* bias     = (const float*)d_in[5];
    float* out = (float*)d_out;

    cudaFuncSetAttribute(fused_kernel, cudaFuncAttributeMaxDynamicSharedMemorySize,
                         DYN_SMEM);
    convert_wb_kernel<<<16, 256>>>(W, bias);
    dim3 g(NTILES, B_);
    fused_kernel<<<g, THREADS, DYN_SMEM>>>(times, features, mask, usample, out);
}